// round 16
// baseline (speedup 1.0000x reference)
#include <cuda_runtime.h>
#include <cstdint>

// Paillier 2x2 "sum" pooling = windowed modular product of ciphertexts mod n^2.
// n = 46337, NSQ = n^2 = 2147117569 < 2^31. Input int32, output float32.
//
// Montgomery multiplication with R = 2^32, lazy residues in [0, 2N):
//   mm(mm(mm(mm(a,b),c),d), R^4 mod N) == a*b*c*d mod N  (one final fixup)
//
// Evidence: R10 (dense 4ch + .CS) = 94.1-94.4us, 85.7% of HBM spec, stable.
// R16 experiment: sm_100a 256-bit loads/stores (ld/st.global.cs.v8.b32).
// 8 channels/thread as ONE 32B load per window position -> per-instruction
// dense (unlike R9's two stride-2 16B loads), half the LDG/STG count.

static constexpr uint32_t NSQ = 2147117569u;  // 46337^2

static constexpr uint32_t compute_np() {
    uint32_t inv = NSQ;
    for (int i = 0; i < 5; ++i) inv *= (2u - NSQ * inv);
    return (uint32_t)(0u - inv);
}
static constexpr uint32_t NPRIME = compute_np();

static constexpr uint32_t compute_r4() {
    uint64_t r = 1;
    for (int i = 0; i < 128; ++i) r = (r * 2u) % (uint64_t)NSQ;
    return (uint32_t)r;
}
static constexpr uint32_t R4 = compute_r4();

__device__ __forceinline__ uint32_t montmul(uint32_t a, uint32_t b) {
    uint64_t t = (uint64_t)a * (uint64_t)b;         // IMAD.WIDE
    uint32_t m = (uint32_t)t * NPRIME;              // IMAD (lo32)
    uint64_t u = t + (uint64_t)m * (uint64_t)NSQ;   // IMAD.WIDE (64-bit acc)
    return (uint32_t)(u >> 32);
}

__device__ __forceinline__ float pool4(uint32_t a, uint32_t b,
                                       uint32_t c, uint32_t d) {
    uint32_t x = montmul(a, b);   // < 2N
    x = montmul(x, c);            // < 2N
    x = montmul(x, d);            // < 2N
    x = montmul(x, R4);           // abcd mod' N, < 2N
    uint32_t y = x - NSQ;
    x = min(x, y);                // branchless final reduce
    return (float)x;
}

// 256-bit streaming load/store (sm_100a, PTX 8.7). 32B-aligned addresses.
__device__ __forceinline__ void ldg256cs(const uint32_t* p, uint32_t* r) {
    asm volatile("ld.global.cs.v8.b32 {%0,%1,%2,%3,%4,%5,%6,%7}, [%8];"
                 : "=r"(r[0]), "=r"(r[1]), "=r"(r[2]), "=r"(r[3]),
                   "=r"(r[4]), "=r"(r[5]), "=r"(r[6]), "=r"(r[7])
                 : "l"(p));
}
__device__ __forceinline__ void stg256cs(float* p, const uint32_t* r) {
    asm volatile("st.global.cs.v8.b32 [%0], {%1,%2,%3,%4,%5,%6,%7,%8};"
                 :: "l"(p),
                    "r"(r[0]), "r"(r[1]), "r"(r[2]), "r"(r[3]),
                    "r"(r[4]), "r"(r[5]), "r"(r[6]), "r"(r[7])
                 : "memory");
}

// Shapes: B=32, H=256, W=256, C=64 -> Ho=Wo=128. int32 in, float32 out.
// Each thread: 8 adjacent channels, 4x LDG.256 + 1x STG.256.
// Threads = 32*128*128*8 = 4,194,304. Lanes 0-7 cover 256B contiguous.
__global__ __launch_bounds__(256)
void paillier_pool_kernel(const uint32_t* __restrict__ in,
                          float* __restrict__ out) {
    uint32_t tid = blockIdx.x * 256u + threadIdx.x;

    uint32_t c8  = tid & 7u;           // channel group  [0,8)
    uint32_t wo  = (tid >> 3) & 127u;  // output col     [0,128)
    uint32_t hob = tid >> 10;          // b*128 + ho     [0,4096)

    // Input elem idx (b, 2ho, 2wo, 8c8) = hob*32768 + wo*128 + 8c8.
    // Row stride (h+1) = W*C = 16384 elem; col stride (w+1) = 64 elem.
    const uint32_t* p = in + (hob * 32768u + wo * 128u + 8u * c8);

    uint32_t a[8], b[8], c[8], d[8];
    ldg256cs(p,            a);   // (h=2ho,   w=2wo)
    ldg256cs(p + 64u,      b);   // (h=2ho,   w=2wo+1)
    ldg256cs(p + 16384u,   c);   // (h=2ho+1, w=2wo)
    ldg256cs(p + 16448u,   d);   // (h=2ho+1, w=2wo+1)

    uint32_t r[8];
#pragma unroll
    for (int i = 0; i < 8; ++i)
        r[i] = __float_as_uint(pool4(a[i], b[i], c[i], d[i]));

    // Output elem idx (b, ho, wo, 8c8) = hob*8192 + wo*64 + 8c8.
    stg256cs(out + (hob * 8192u + wo * 64u + 8u * c8), r);
}

extern "C" void kernel_launch(void* const* d_in, const int* in_sizes, int n_in,
                              void* d_out, int out_size) {
    (void)in_sizes; (void)n_in; (void)out_size;
    const uint32_t* in = (const uint32_t*)d_in[0];
    float* out = (float*)d_out;
    // 4,194,304 threads / 256 = 16384 blocks
    paillier_pool_kernel<<<16384, 256>>>(in, out);
}

// round 17
// speedup vs baseline: 1.0026x; 1.0026x over previous
#include <cuda_runtime.h>
#include <cstdint>

// Paillier 2x2 "sum" pooling = windowed modular product of ciphertexts mod n^2.
// n = 46337, NSQ = n^2 = 2147117569 < 2^31. Input int32, output float32.
//
// Montgomery multiplication with R = 2^32, lazy residues in [0, 2N):
//   mm(mm(mm(mm(a,b),c),d), R^4 mod N) == a*b*c*d mod N  (one final fixup)
// 3 IMAD-class instructions per montmul -> 12 fma-pipe ops per output.
//
// FINAL (R10 configuration). Evidence trail:
//   R8  dense 4ch/thread:        94.5us, DRAM 84.6%
//   R9  8ch stride-2:            96.6us REGRESS (L1 46%: broken coalescing)
//   R10 R8 + .CS hints:          94.1us, 6.85 TB/s = 85.7% of spec  <- BEST
//   R11 2 far units (MLP 8):     95.0us neutral (LSU queue not limiting)
//   R12 512-thread blocks:       94.6us neutral
//   R13 persistent single-wave:  104.2us REGRESS (lost CTA-scheduler overlap)
//   R15 R10 re-confirm:          94.4us (stable)
//   R16 256-bit v8.b32 ld/st:    94.9us neutral (HBM 86.3%; L1 unchanged)
// Kernel is pinned at the HBM streaming ceiling for a 4:1 read:write
// single-touch stream; traffic (512 MiB in + 128 MiB out) is minimal and
// compute sits at ~20% of the IMAD pipe. No kernel-addressable headroom left.

static constexpr uint32_t NSQ = 2147117569u;  // 46337^2

static constexpr uint32_t compute_np() {
    uint32_t inv = NSQ;
    for (int i = 0; i < 5; ++i) inv *= (2u - NSQ * inv);
    return (uint32_t)(0u - inv);
}
static constexpr uint32_t NPRIME = compute_np();

static constexpr uint32_t compute_r4() {
    uint64_t r = 1;
    for (int i = 0; i < 128; ++i) r = (r * 2u) % (uint64_t)NSQ;
    return (uint32_t)r;
}
static constexpr uint32_t R4 = compute_r4();

__device__ __forceinline__ uint32_t montmul(uint32_t a, uint32_t b) {
    uint64_t t = (uint64_t)a * (uint64_t)b;         // IMAD.WIDE
    uint32_t m = (uint32_t)t * NPRIME;              // IMAD (lo32)
    uint64_t u = t + (uint64_t)m * (uint64_t)NSQ;   // IMAD.WIDE (64-bit acc)
    return (uint32_t)(u >> 32);
}

__device__ __forceinline__ float pool4(uint32_t a, uint32_t b,
                                       uint32_t c, uint32_t d) {
    uint32_t x = montmul(a, b);   // < 2N
    x = montmul(x, c);            // < 2N
    x = montmul(x, d);            // < 2N
    x = montmul(x, R4);           // abcd mod' N, < 2N
    uint32_t y = x - NSQ;
    x = min(x, y);                // branchless final reduce
    return (float)x;
}

// Shapes: B=32, H=256, W=256, C=64 -> Ho=Wo=128. int32 in, float32 out.
// Each thread produces 4 adjacent channels (uint4 in, float4 out), with
// per-instruction-dense warp access: threads 0-15 cover 256B contiguous.
// Threads = 32*128*128*16 = 8,388,608.
__global__ __launch_bounds__(256)
void paillier_pool_kernel(const uint4* __restrict__ in,
                          float4* __restrict__ out) {
    uint32_t tid = blockIdx.x * 256u + threadIdx.x;

    uint32_t c4  = tid & 15u;          // channel group  [0,16)
    uint32_t wo  = (tid >> 4) & 127u;  // output col     [0,128)
    uint32_t hob = tid >> 11;          // b*128 + ho     [0,4096)

    // Input elem idx (b, 2ho, 2wo, 4c4) = hob*32768 + wo*128 + 4c4.
    // uint4 units: base = hob*8192 + wo*32 + c4. Row stride (h+1) = 4096 uint4.
    uint32_t base = hob * 8192u + wo * 32u + c4;
    const uint4* p = in + base;

    // Front-batched streaming loads (4x LDG.E.128, evict-first).
    uint4 v00 = __ldcs(p);            // (h=2ho,   w=2wo)
    uint4 v01 = __ldcs(p + 16u);      // (h=2ho,   w=2wo+1)
    uint4 v10 = __ldcs(p + 4096u);    // (h=2ho+1, w=2wo)
    uint4 v11 = __ldcs(p + 4112u);    // (h=2ho+1, w=2wo+1)

    float4 r;
    r.x = pool4(v00.x, v01.x, v10.x, v11.x);
    r.y = pool4(v00.y, v01.y, v10.y, v11.y);
    r.z = pool4(v00.z, v01.z, v10.z, v11.z);
    r.w = pool4(v00.w, v01.w, v10.w, v11.w);

    // Output elem idx (b, ho, wo, 4c4): float4 units = hob*2048 + wo*16 + c4.
    __stcs(out + (hob * 2048u + wo * 16u + c4), r);
}

extern "C" void kernel_launch(void* const* d_in, const int* in_sizes, int n_in,
                              void* d_out, int out_size) {
    (void)in_sizes; (void)n_in; (void)out_size;
    const uint4* in = (const uint4*)d_in[0];
    float4* out = (float4*)d_out;
    // 8,388,608 threads / 256 = 32768 blocks
    paillier_pool_kernel<<<32768, 256>>>(in, out);
}